// round 17
// baseline (speedup 1.0000x reference)
#include <cuda_runtime.h>
#include <cuda_bf16.h>
#include <cstdint>

// -------- scratch (device globals; no allocation allowed) --------
#define NMAX 100000
#define EMAX 1600000
#define NB_MAX 128            // ceil(NMAX/1024) = 98 <= 128

__device__ __align__(16) float g_mean[(size_t)NMAX * 32]; // mean of neighbor x rows
__device__ __align__(16) float g_z2[(size_t)NMAX * 16];   // h @ W2l
__device__ __align__(16) float g_r2[(size_t)NMAX * 16];   // h @ W2r + b2
__device__ int g_rowptr[NMAX + 1];
__device__ int g_cnt[NMAX];      // zero-initialized at load; re-zeroed by scan23 each run
__device__ int g_cursor[NMAX];
__device__ int g_csr_src[EMAX];
__device__ int g_bsum[NB_MAX];

// Per-warp dtype sniff: int64 iff the first 32 odd 32-bit words are all zero.
__device__ __forceinline__ int sniff_is64(const void* ei) {
    unsigned w = ((const unsigned*)ei)[2 * (threadIdx.x & 31) + 1];
    return __ballot_sync(0xffffffffu, w != 0u) == 0u;
}

// -------- count in-degree: 4 edges/thread (2 independent 16B index loads) --------
__global__ void count_kernel(const void* __restrict__ ei,
                             int* __restrict__ cnt, int E, int N) {
    int is64 = sniff_is64(ei);
    int stride = gridDim.x * blockDim.x;
    int Q = E >> 2;   // E divisible by 4
    if (is64) {
        const longlong2* p = (const longlong2*)((const long long*)ei + E);
        for (int q = blockIdx.x * blockDim.x + threadIdx.x; q < Q; q += stride) {
            longlong2 a = p[2 * q];
            longlong2 b = p[2 * q + 1];
            int d0 = (int)a.x, d1 = (int)a.y, d2 = (int)b.x, d3 = (int)b.y;
            if (d0 >= 0 && d0 < N) atomicAdd(&cnt[d0], 1);
            if (d1 >= 0 && d1 < N) atomicAdd(&cnt[d1], 1);
            if (d2 >= 0 && d2 < N) atomicAdd(&cnt[d2], 1);
            if (d3 >= 0 && d3 < N) atomicAdd(&cnt[d3], 1);
        }
    } else {
        const int4* p = (const int4*)((const int*)ei + E);
        for (int q = blockIdx.x * blockDim.x + threadIdx.x; q < Q; q += stride) {
            int4 v = p[q];
            if (v.x >= 0 && v.x < N) atomicAdd(&cnt[v.x], 1);
            if (v.y >= 0 && v.y < N) atomicAdd(&cnt[v.y], 1);
            if (v.z >= 0 && v.z < N) atomicAdd(&cnt[v.z], 1);
            if (v.w >= 0 && v.w < N) atomicAdd(&cnt[v.w], 1);
        }
    }
}

// -------- scan stage 1: shfl warp scans (2 syncs) --------
__global__ void scan1_kernel(const int* __restrict__ cnt,
                             int* __restrict__ rowptr,
                             int* __restrict__ bsum, int N) {
    __shared__ int wsum[32];
    int lane = threadIdx.x & 31;
    int wid = threadIdx.x >> 5;
    int gid = blockIdx.x * 1024 + threadIdx.x;
    int v = (gid < N) ? cnt[gid] : 0;

    int inc = v;
#pragma unroll
    for (int off = 1; off < 32; off <<= 1) {
        int t = __shfl_up_sync(0xffffffffu, inc, off);
        if (lane >= off) inc += t;
    }
    if (lane == 31) wsum[wid] = inc;
    __syncthreads();
    if (wid == 0) {
        int wi = wsum[lane];
#pragma unroll
        for (int off = 1; off < 32; off <<= 1) {
            int t = __shfl_up_sync(0xffffffffu, wi, off);
            if (lane >= off) wi += t;
        }
        wsum[lane] = wi;   // inclusive warp totals
    }
    __syncthreads();
    int base = (wid > 0) ? wsum[wid - 1] : 0;
    if (gid < N) rowptr[gid] = base + inc - v;   // exclusive within block
    if (threadIdx.x == 1023) bsum[blockIdx.x] = wsum[31];
}

// -------- scan stage 2+3: single-warp shfl scan; finalize rowptr;
//          cursor = rowptr; re-zero cnt for next run --------
__global__ void scan23_kernel(int* __restrict__ rowptr,
                              const int* __restrict__ bsum,
                              int* __restrict__ cursor,
                              int* __restrict__ cnt, int N, int E, int nb) {
    __shared__ int sb[NB_MAX];
    if (threadIdx.x < 32) {
        int lane = threadIdx.x;
        int a0 = (lane * 4 + 0 < nb) ? bsum[lane * 4 + 0] : 0;
        int a1 = (lane * 4 + 1 < nb) ? bsum[lane * 4 + 1] : 0;
        int a2 = (lane * 4 + 2 < nb) ? bsum[lane * 4 + 2] : 0;
        int a3 = (lane * 4 + 3 < nb) ? bsum[lane * 4 + 3] : 0;
        int s0 = a0, s1 = s0 + a1, s2 = s1 + a2, s3 = s2 + a3;
        int inc = s3;
#pragma unroll
        for (int off = 1; off < 32; off <<= 1) {
            int t = __shfl_up_sync(0xffffffffu, inc, off);
            if (lane >= off) inc += t;
        }
        int base = inc - s3;
        sb[lane * 4 + 0] = base + s0;
        sb[lane * 4 + 1] = base + s1;
        sb[lane * 4 + 2] = base + s2;
        sb[lane * 4 + 3] = base + s3;
    }
    __syncthreads();
    int gid = blockIdx.x * blockDim.x + threadIdx.x;
    if (gid < N) {
        int w = gid >> 10;
        int rp = rowptr[gid] + ((w > 0) ? sb[w - 1] : 0);
        rowptr[gid] = rp;
        cursor[gid] = rp;          // absolute write pointer
        cnt[gid] = 0;              // reset for next graph replay
    }
    if (gid == 0) rowptr[N] = E;
}

// -------- fill CSR: 4 edges/thread, 4 independent atomic->store chains --------
__global__ void fill_kernel(const void* __restrict__ ei,
                            int* __restrict__ cursor,
                            int* __restrict__ csr_src, int E, int N) {
    int is64 = sniff_is64(ei);
    int stride = gridDim.x * blockDim.x;
    int Q = E >> 2;
    for (int q = blockIdx.x * blockDim.x + threadIdx.x; q < Q; q += stride) {
        int s0, s1, s2, s3, d0, d1, d2, d3;
        if (is64) {
            const longlong2* ps = (const longlong2*)ei;
            const longlong2* pd = (const longlong2*)((const long long*)ei + E);
            longlong2 sa = ps[2 * q], sb = ps[2 * q + 1];
            longlong2 da = pd[2 * q], db = pd[2 * q + 1];
            s0 = (int)sa.x; s1 = (int)sa.y; s2 = (int)sb.x; s3 = (int)sb.y;
            d0 = (int)da.x; d1 = (int)da.y; d2 = (int)db.x; d3 = (int)db.y;
        } else {
            const int4* ps = (const int4*)ei;
            const int4* pd = (const int4*)((const int*)ei + E);
            int4 sv = ps[q], dv = pd[q];
            s0 = sv.x; s1 = sv.y; s2 = sv.z; s3 = sv.w;
            d0 = dv.x; d1 = dv.y; d2 = dv.z; d3 = dv.w;
        }
        // 4 independent atomic->store chains (overlapped latencies)
        bool v0 = (d0 >= 0 && d0 < N);
        bool v1 = (d1 >= 0 && d1 < N);
        bool v2 = (d2 >= 0 && d2 < N);
        bool v3 = (d3 >= 0 && d3 < N);
        int p0 = v0 ? atomicAdd(&cursor[d0], 1) : 0;
        int p1 = v1 ? atomicAdd(&cursor[d1], 1) : 0;
        int p2 = v2 ? atomicAdd(&cursor[d2], 1) : 0;
        int p3 = v3 ? atomicAdd(&cursor[d3], 1) : 0;
        if (v0) csr_src[p0] = s0;
        if (v1) csr_src[p1] = s1;
        if (v2) csr_src[p2] = s2;
        if (v3) csr_src[p3] = s3;
    }
}

// -------- gather 1: mean[n] = (1/deg) * sum_{s in N(n)} x[s]   (rows 128B) --------
// Warp per node. 4 groups x 8 lanes; stride 8 -> 8 rows in flight per warp.
__global__ void gather1_kernel(const float* __restrict__ x,
                               const int* __restrict__ rowptr,
                               const int* __restrict__ csr_src,
                               float* __restrict__ mean, int N) {
    int lane = threadIdx.x & 31;
    int g = lane >> 3;          // 0..3
    int c = lane & 7;           // 0..7
    int n = blockIdx.x * (blockDim.x >> 5) + (threadIdx.x >> 5);
    if (n >= N) return;

    int s0 = rowptr[n];
    int s1 = rowptr[n + 1];
    int deg = s1 - s0;

    float4 a0 = make_float4(0.f, 0.f, 0.f, 0.f);
    float4 a1 = make_float4(0.f, 0.f, 0.f, 0.f);
    for (int e = s0; e < s1; e += 8) {         // warp-uniform bound
        int i0 = e + g;
        int i1 = e + 4 + g;
        bool v0 = i0 < s1;
        bool v1 = i1 < s1;
        int sid0 = v0 ? csr_src[i0] : 0;
        int sid1 = v1 ? csr_src[i1] : 0;
        float4 r0 = ((const float4*)(x + (size_t)sid0 * 32))[c];
        float4 r1 = ((const float4*)(x + (size_t)sid1 * 32))[c];
        if (v0) { a0.x += r0.x; a0.y += r0.y; a0.z += r0.z; a0.w += r0.w; }
        if (v1) { a1.x += r1.x; a1.y += r1.y; a1.z += r1.z; a1.w += r1.w; }
    }
    a0.x += a1.x; a0.y += a1.y; a0.z += a1.z; a0.w += a1.w;
#pragma unroll
    for (int s = 8; s <= 16; s <<= 1) {
        a0.x += __shfl_xor_sync(0xffffffffu, a0.x, s);
        a0.y += __shfl_xor_sync(0xffffffffu, a0.y, s);
        a0.z += __shfl_xor_sync(0xffffffffu, a0.z, s);
        a0.w += __shfl_xor_sync(0xffffffffu, a0.w, s);
    }
    if (g == 0) {
        float inv = 1.0f / (float)max(deg, 1);
        float4 m = make_float4(a0.x * inv, a0.y * inv, a0.z * inv, a0.w * inv);
        ((float4*)(mean + (size_t)n * 32))[c] = m;
    }
}

// -------- fused dense: h = relu(mean@W1l + x@W1r + b1); z2 = h@W2l; r2 = h@W2r + b2 --------
__global__ void dense_kernel(const float* __restrict__ x,
                             const float* __restrict__ mean,
                             const float* __restrict__ W1l,
                             const float* __restrict__ W1r,
                             const float* __restrict__ b1,
                             const float* __restrict__ W2l,
                             const float* __restrict__ W2r,
                             const float* __restrict__ b2,
                             float* __restrict__ z2,
                             float* __restrict__ r2, int N) {
    int lane = threadIdx.x & 31;
    int warp = (blockIdx.x * blockDim.x + threadIdx.x) >> 5;
    int nwarps = (gridDim.x * blockDim.x) >> 5;

    float wl1[32], wr1[32], w2[32];
#pragma unroll
    for (int k = 0; k < 32; k++) {
        wl1[k] = W1l[k * 32 + lane];
        wr1[k] = W1r[k * 32 + lane];
    }
    int j = lane & 15;
    bool left = lane < 16;
#pragma unroll
    for (int k = 0; k < 32; k++)
        w2[k] = left ? W2l[k * 16 + j] : W2r[k * 16 + j];
    float b1j = b1[lane];
    float b2j = left ? 0.0f : b2[j];

    for (int n = warp; n < N; n += nwarps) {
        float mv = mean[(size_t)n * 32 + lane];
        float xv = x[(size_t)n * 32 + lane];

        float r = b1j;
#pragma unroll
        for (int k = 0; k < 32; k++) {
            float mk = __shfl_sync(0xffffffffu, mv, k);
            float xk = __shfl_sync(0xffffffffu, xv, k);
            r = fmaf(mk, wl1[k], fmaf(xk, wr1[k], r));
        }
        float h = fmaxf(r, 0.0f);

        float acc = b2j;
#pragma unroll
        for (int k = 0; k < 32; k++) {
            float hk = __shfl_sync(0xffffffffu, h, k);
            acc = fmaf(hk, w2[k], acc);
        }
        if (left) z2[(size_t)n * 16 + j] = acc;
        else      r2[(size_t)n * 16 + j] = acc;
    }
}

// -------- gather 2: out[n] = (1/deg) * sum_{s} z2[s] + r2[n]   (rows 64B) --------
// Warp per node. 8 groups x 4 lanes; stride 16 -> 16 rows in flight per warp.
__global__ void gather2_kernel(const float* __restrict__ z2,
                               const float* __restrict__ r2,
                               const int* __restrict__ rowptr,
                               const int* __restrict__ csr_src,
                               float* __restrict__ out, int N) {
    int lane = threadIdx.x & 31;
    int g = lane >> 2;          // 0..7
    int c = lane & 3;           // 0..3
    int n = blockIdx.x * (blockDim.x >> 5) + (threadIdx.x >> 5);
    if (n >= N) return;

    int s0 = rowptr[n];
    int s1 = rowptr[n + 1];
    int deg = s1 - s0;

    float4 a0 = make_float4(0.f, 0.f, 0.f, 0.f);
    float4 a1 = make_float4(0.f, 0.f, 0.f, 0.f);
    for (int e = s0; e < s1; e += 16) {        // warp-uniform bound
        int i0 = e + g;
        int i1 = e + 8 + g;
        bool v0 = i0 < s1;
        bool v1 = i1 < s1;
        int sid0 = v0 ? csr_src[i0] : 0;
        int sid1 = v1 ? csr_src[i1] : 0;
        float4 r0 = ((const float4*)(z2 + (size_t)sid0 * 16))[c];
        float4 r1 = ((const float4*)(z2 + (size_t)sid1 * 16))[c];
        if (v0) { a0.x += r0.x; a0.y += r0.y; a0.z += r0.z; a0.w += r0.w; }
        if (v1) { a1.x += r1.x; a1.y += r1.y; a1.z += r1.z; a1.w += r1.w; }
    }
    a0.x += a1.x; a0.y += a1.y; a0.z += a1.z; a0.w += a1.w;
#pragma unroll
    for (int s = 4; s <= 16; s <<= 1) {
        a0.x += __shfl_xor_sync(0xffffffffu, a0.x, s);
        a0.y += __shfl_xor_sync(0xffffffffu, a0.y, s);
        a0.z += __shfl_xor_sync(0xffffffffu, a0.z, s);
        a0.w += __shfl_xor_sync(0xffffffffu, a0.w, s);
    }
    if (g == 0) {
        float inv = 1.0f / (float)max(deg, 1);
        float4 rr = ((const float4*)(r2 + (size_t)n * 16))[c];
        float4 o = make_float4(a0.x * inv + rr.x, a0.y * inv + rr.y,
                               a0.z * inv + rr.z, a0.w * inv + rr.w);
        ((float4*)(out + (size_t)n * 16))[c] = o;
    }
}

extern "C" void kernel_launch(void* const* d_in, const int* in_sizes, int n_in,
                              void* d_out, int out_size) {
    const float* x   = (const float*)d_in[0];
    const void*  ei  = d_in[1];
    const float* W1l = (const float*)d_in[2];
    const float* W1r = (const float*)d_in[3];
    const float* b1  = (const float*)d_in[4];
    const float* W2l = (const float*)d_in[5];
    const float* W2r = (const float*)d_in[6];
    const float* b2  = (const float*)d_in[7];
    float* out = (float*)d_out;

    int N = in_sizes[0] / 32;   // 100000
    int E = in_sizes[1] / 2;    // 1600000

    float *mean, *z2, *r2;
    int *rowptr, *cnt, *cursor, *csr_src, *bsum;
    cudaGetSymbolAddress((void**)&mean, g_mean);
    cudaGetSymbolAddress((void**)&z2, g_z2);
    cudaGetSymbolAddress((void**)&r2, g_r2);
    cudaGetSymbolAddress((void**)&rowptr, g_rowptr);
    cudaGetSymbolAddress((void**)&cnt, g_cnt);
    cudaGetSymbolAddress((void**)&cursor, g_cursor);
    cudaGetSymbolAddress((void**)&csr_src, g_csr_src);
    cudaGetSymbolAddress((void**)&bsum, g_bsum);

    int nb = (N + 1023) / 1024;           // 98
    int gblocks = (N + 7) / 8;            // 8 warps per 256-thread block
    int Q = E >> 2;                       // 400000 quads
    int qblocks = (Q + 255) / 256;        // 1563

    // ---- CSR build (4 launches; cnt starts zero: load-time init + scan23 reset) ----
    count_kernel<<<qblocks, 256>>>(ei, cnt, E, N);
    scan1_kernel<<<nb, 1024>>>(cnt, rowptr, bsum, N);
    scan23_kernel<<<(N + 255) / 256, 256>>>(rowptr, bsum, cursor, cnt, N, E, nb);
    fill_kernel<<<qblocks, 256>>>(ei, cursor, csr_src, E, N);

    // ---- layer 1 gather ----
    gather1_kernel<<<gblocks, 256>>>(x, rowptr, csr_src, mean, N);
    // ---- fused dense ----
    dense_kernel<<<2048, 256>>>(x, mean, W1l, W1r, b1, W2l, W2r, b2, z2, r2, N);
    // ---- layer 2 gather + epilogue ----
    gather2_kernel<<<gblocks, 256>>>(z2, r2, rowptr, csr_src, out, N);
}